// round 2
// baseline (speedup 1.0000x reference)
#include <cuda_runtime.h>

#define NB 4
#define NS 2048
#define ND 1024
#define NH 16
#define HD 64
#define NEGV (-10000.0f)
#define SCALE 0.125f
#define SROW 2049   // padded score row stride (2048+1) to kill bank conflicts

// ---------------- scratch (static device arrays; no runtime allocation) ------------
__device__ float g_qh[NB * NH * NS * HD];   // [b,h,s,dk]
__device__ float g_kh[NB * NH * NS * HD];
__device__ float g_vh[NB * NH * NS * HD];
__device__ float g_ao[NB * NS * ND];        // attention output pre-LN, [b,s,h*dv+d]

// ---------------- QKV projection: Y = X @ W^T + b, scattered to [b,h,s,d] ----------
// 128x128 tile, BK=8, 256 threads, 8x8 micro-tile per thread.
__global__ __launch_bounds__(256) void proj_kernel(
    const float* __restrict__ X, const float* __restrict__ W,
    const float* __restrict__ bias, int which)
{
    __shared__ __align__(16) float As[8][132];
    __shared__ __align__(16) float Bs[8][132];
    float* out = (which == 0) ? g_qh : (which == 1) ? g_kh : g_vh;

    const int t  = threadIdx.x;
    const int m0 = blockIdx.x * 128;
    const int n0 = blockIdx.y * 128;
    const int tm = (t & 15) * 8;
    const int tn = (t >> 4) * 8;

    float acc[8][8];
#pragma unroll
    for (int i = 0; i < 8; i++)
#pragma unroll
        for (int j = 0; j < 8; j++) acc[i][j] = 0.0f;

    const int lr = t >> 1;          // 0..127
    const int lk = (t & 1) * 4;     // 0 or 4

    for (int k0 = 0; k0 < ND; k0 += 8) {
        float4 av = *(const float4*)(X + (size_t)(m0 + lr) * ND + k0 + lk);
        float4 bv = *(const float4*)(W + (size_t)(n0 + lr) * ND + k0 + lk);
        As[lk + 0][lr] = av.x; As[lk + 1][lr] = av.y; As[lk + 2][lr] = av.z; As[lk + 3][lr] = av.w;
        Bs[lk + 0][lr] = bv.x; Bs[lk + 1][lr] = bv.y; Bs[lk + 2][lr] = bv.z; Bs[lk + 3][lr] = bv.w;
        __syncthreads();
#pragma unroll
        for (int kk = 0; kk < 8; kk++) {
            float a[8], bb[8];
            *(float4*)&a[0]  = *(const float4*)&As[kk][tm];
            *(float4*)&a[4]  = *(const float4*)&As[kk][tm + 4];
            *(float4*)&bb[0] = *(const float4*)&Bs[kk][tn];
            *(float4*)&bb[4] = *(const float4*)&Bs[kk][tn + 4];
#pragma unroll
            for (int i = 0; i < 8; i++)
#pragma unroll
                for (int j = 0; j < 8; j++) acc[i][j] += a[i] * bb[j];
        }
        __syncthreads();
    }

#pragma unroll
    for (int i = 0; i < 8; i++) {
        const int row = m0 + tm + i;      // b*S + s
        const int b = row / NS, s = row % NS;
#pragma unroll
        for (int j = 0; j < 8; j++) {
            const int col = n0 + tn + j;  // h*64 + d
            const int h = col >> 6, d = col & 63;
            out[(((size_t)b * NH + h) * NS + s) * HD + d] = acc[i][j] + bias[col];
        }
    }
}

// ---------------- attention: one block per (b, h, 16-query tile) -------------------
// smem layout: scores[16][2049] | Ks[64][68] (reused as PV partial buf) | inv_s[16]
__global__ __launch_bounds__(256) void attn_kernel(const int* __restrict__ mask,
                                                   float* __restrict__ attn_out)
{
    extern __shared__ __align__(16) float sm[];
    float* scores = sm;                       // 16*2049 = 32784 floats
    float* Ks     = sm + 16 * SROW;           // 64*68  = 4352 floats (and PV partials)
    float* inv_s  = Ks + 64 * 68;             // 16 floats

    const int t   = threadIdx.x;
    const int bid = blockIdx.x;
    const int qt = bid & 127;
    const int h  = (bid >> 7) & 15;
    const int b  = bid >> 11;
    const int q0 = qt * 16;

    const size_t bh = (size_t)(b * NH + h);
    const float* qbase = g_qh + bh * NS * HD;
    const float* kbase = g_kh + bh * NS * HD;
    const float* vbase = g_vh + bh * NS * HD;

    // ---- phase 1: raw scores = (q*scale) . K, q rows register-resident ----
    {
        const int i   = t & 15;
        const int jb2 = t >> 4;       // 0..15
        float4 qr[16];
        const float* qp = qbase + (size_t)(q0 + i) * HD;
#pragma unroll
        for (int kq = 0; kq < 16; kq++) {
            float4 qv = *(const float4*)(qp + kq * 4);
            qv.x *= SCALE; qv.y *= SCALE; qv.z *= SCALE; qv.w *= SCALE;
            qr[kq] = qv;
        }
        for (int jc = 0; jc < 32; jc++) {
            const int j0 = jc * 64;
#pragma unroll
            for (int r = 0; r < 4; r++) {
                const int idx = t + 256 * r;
                const int j = idx >> 4, kq = idx & 15;
                float4 kv = *(const float4*)(kbase + (size_t)(j0 + j) * HD + kq * 4);
                *(float4*)(Ks + j * 68 + kq * 4) = kv;
            }
            __syncthreads();
            float4 accv[4];
#pragma unroll
            for (int m = 0; m < 4; m++) accv[m] = make_float4(0.f, 0.f, 0.f, 0.f);
#pragma unroll
            for (int kq = 0; kq < 16; kq++) {
                const float4 qv = qr[kq];
#pragma unroll
                for (int m = 0; m < 4; m++) {
                    const float4 kv = *(const float4*)(Ks + (jb2 + 16 * m) * 68 + kq * 4);
                    accv[m].x += qv.x * kv.x; accv[m].y += qv.y * kv.y;
                    accv[m].z += qv.z * kv.z; accv[m].w += qv.w * kv.w;
                }
            }
#pragma unroll
            for (int m = 0; m < 4; m++)
                scores[i * SROW + j0 + jb2 + 16 * m] =
                    (accv[m].x + accv[m].y) + (accv[m].z + accv[m].w);
            __syncthreads();
        }
    }

    // ---- phase 2: masks + softmax (warp w owns rows 2w, 2w+1; coalesced mask) ----
    {
        const int w = t >> 5, lane = t & 31;
        for (int rr = 0; rr < 2; rr++) {
            const int i = w * 2 + rr;
            const int qrow = q0 + i;
            const int* mrow = mask + ((size_t)b * NS + qrow) * NS;
            float mx = -3.0e38f;
            for (int k = lane; k < NS; k += 32) {
                float sv = scores[i * SROW + k];
                sv += (1.0f - (float)mrow[k]) * NEGV;   // padding mask adder
                if (k > qrow) sv += NEGV;               // causal adder
                scores[i * SROW + k] = sv;
                mx = fmaxf(mx, sv);
            }
#pragma unroll
            for (int o = 16; o > 0; o >>= 1) mx = fmaxf(mx, __shfl_xor_sync(0xffffffffu, mx, o));
            float sum = 0.0f;
            for (int k = lane; k < NS; k += 32) {
                const float p = __expf(scores[i * SROW + k] - mx);
                scores[i * SROW + k] = p;
                sum += p;
            }
#pragma unroll
            for (int o = 16; o > 0; o >>= 1) sum += __shfl_xor_sync(0xffffffffu, sum, o);
            if (lane == 0) inv_s[i] = 1.0f / sum;
        }
        __syncthreads();
    }

    // ---- phase 3: write normalized attention probabilities (if requested) ----
    if (attn_out) {
        for (int idx = t; idx < 16 * NS; idx += 256) {
            const int i = idx >> 11, j = idx & (NS - 1);
            attn_out[(bh * NS + q0 + i) * (size_t)NS + j] = scores[i * SROW + j] * inv_s[i];
        }
    }

    // ---- phase 4: PV with k split into 4 partitions, smem partial reduce ----
    {
        const int p  = t >> 6;          // k partition 0..3
        const int u  = t & 63;
        const int i4 = u & 3;           // row group (4 rows each)
        const int d  = (u >> 2) * 4;    // 0..60 step 4
        float4 acc[4];
#pragma unroll
        for (int r = 0; r < 4; r++) acc[r] = make_float4(0.f, 0.f, 0.f, 0.f);
        const int kbeg = p * 512;
        for (int k = kbeg; k < kbeg + 512; k++) {
            const float4 vv = *(const float4*)(vbase + (size_t)k * HD + d);
#pragma unroll
            for (int r = 0; r < 4; r++) {
                const float pp = scores[(i4 * 4 + r) * SROW + k];
                acc[r].x += pp * vv.x; acc[r].y += pp * vv.y;
                acc[r].z += pp * vv.z; acc[r].w += pp * vv.w;
            }
        }
#pragma unroll
        for (int r = 0; r < 4; r++)
            *(float4*)(Ks + ((p * 16) + i4 * 4 + r) * 64 + d) = acc[r];
        __syncthreads();
        for (int idx = t; idx < 1024; idx += 256) {
            const int i = idx >> 6, dd = idx & 63;
            const float s2 = Ks[(0 * 16 + i) * 64 + dd] + Ks[(1 * 16 + i) * 64 + dd] +
                             Ks[(2 * 16 + i) * 64 + dd] + Ks[(3 * 16 + i) * 64 + dd];
            g_ao[((size_t)b * NS + q0 + i) * ND + h * HD + dd] = s2 * inv_s[i];
        }
    }
}

// ---------------- residual + LayerNorm, one block per (b,s) row --------------------
__global__ __launch_bounds__(256) void ln_kernel(const float* __restrict__ resid,
                                                 const float* __restrict__ gam,
                                                 const float* __restrict__ bet,
                                                 float* __restrict__ out)
{
    __shared__ float xb[ND];
    __shared__ float red[8];
    const int r = blockIdx.x;
    const int t = threadIdx.x;
    const int lane = t & 31, w = t >> 5;
    const size_t base = (size_t)r * ND;

    float lsum = 0.0f;
    for (int j = t; j < ND; j += 256) {
        const float x = g_ao[base + j] + resid[base + j];
        xb[j] = x;
        lsum += x;
    }
#pragma unroll
    for (int o = 16; o > 0; o >>= 1) lsum += __shfl_xor_sync(0xffffffffu, lsum, o);
    if (lane == 0) red[w] = lsum;
    __syncthreads();
    float tot = 0.0f;
#pragma unroll
    for (int w2 = 0; w2 < 8; w2++) tot += red[w2];
    const float mu = tot * (1.0f / ND);
    __syncthreads();

    float lv = 0.0f;
    for (int j = t; j < ND; j += 256) {
        const float dd = xb[j] - mu;
        lv += dd * dd;
    }
#pragma unroll
    for (int o = 16; o > 0; o >>= 1) lv += __shfl_xor_sync(0xffffffffu, lv, o);
    if (lane == 0) red[w] = lv;
    __syncthreads();
    float vtot = 0.0f;
#pragma unroll
    for (int w2 = 0; w2 < 8; w2++) vtot += red[w2];
    const float rstd = rsqrtf(vtot * (1.0f / ND) + 1e-5f);

    for (int j = t; j < ND; j += 256)
        out[base + j] = (xb[j] - mu) * rstd * gam[j] + bet[j];
}

// ---------------- launch -----------------------------------------------------------
extern "C" void kernel_launch(void* const* d_in, const int* in_sizes, int n_in,
                              void* d_out, int out_size)
{
    const float* q    = (const float*)d_in[0];
    const float* k    = (const float*)d_in[1];
    const float* v    = (const float*)d_in[2];
    const int*   mask = (const int*)  d_in[3];
    const float* Wq   = (const float*)d_in[4];
    const float* bq   = (const float*)d_in[5];
    const float* Wk   = (const float*)d_in[6];
    const float* bk   = (const float*)d_in[7];
    const float* Wv   = (const float*)d_in[8];
    const float* bv   = (const float*)d_in[9];
    const float* ln_g = (const float*)d_in[10];
    const float* ln_b = (const float*)d_in[11];
    float* out = (float*)d_out;

    const int smem_bytes = (16 * SROW + 64 * 68 + 16) * (int)sizeof(float);  // 148,672 B
    cudaFuncSetAttribute(attn_kernel, cudaFuncAttributeMaxDynamicSharedMemorySize, smem_bytes);

    dim3 pg(64, 8);  // M=8192/128, N=1024/128
    proj_kernel<<<pg, 256>>>(q, Wq, bq, 0);
    proj_kernel<<<pg, 256>>>(k, Wk, bk, 1);
    proj_kernel<<<pg, 256>>>(v, Wv, bv, 2);

    float* attn = nullptr;
    const long long need = (long long)NB * NS * ND + (long long)NB * NH * NS * NS;
    if ((long long)out_size >= need) attn = out + (size_t)NB * NS * ND;

    attn_kernel<<<NB * NH * (NS / 16), 256, smem_bytes>>>(mask, attn);
    ln_kernel<<<NB * NS, 256>>>(q, ln_g, ln_b, out);
}

// round 4
// speedup vs baseline: 1.4738x; 1.4738x over previous
#include <cuda_runtime.h>

#define NB 4
#define NS 2048
#define ND 1024
#define NH 16
#define HD 64
#define NEGV (-10000.0f)
#define SCALE 0.125f
#define SROW 2052   // padded score row stride; 2052 % 32 == 4 -> conflict-free frags

// ---------------- scratch (static device arrays; no runtime allocation) ------------
__device__ float g_qh[NB * NH * NS * HD];   // [b,h,s,dk]
__device__ float g_kh[NB * NH * NS * HD];
__device__ float g_vh[NB * NH * NS * HD];
__device__ float g_ao[NB * NS * ND];        // attention output pre-LN

// ---------------- tf32 helpers -----------------------------------------------------
__device__ __forceinline__ unsigned f2tf(float x) {
    unsigned u; asm("cvt.rna.tf32.f32 %0, %1;" : "=r"(u) : "f"(x)); return u;
}
__device__ __forceinline__ float f2tff(float x) { return __uint_as_float(f2tf(x)); }

__device__ __forceinline__ void mma_tf32(float c[4], const unsigned a[4], const unsigned b[2]) {
    asm volatile(
        "mma.sync.aligned.m16n8k8.row.col.f32.tf32.tf32.f32 "
        "{%0,%1,%2,%3}, {%4,%5,%6,%7}, {%8,%9}, {%0,%1,%2,%3};"
        : "+f"(c[0]), "+f"(c[1]), "+f"(c[2]), "+f"(c[3])
        : "r"(a[0]), "r"(a[1]), "r"(a[2]), "r"(a[3]), "r"(b[0]), "r"(b[1]));
}

// ---------------- QKV projection: Y = X @ W^T + b, scattered to [b,h,s,d] ----------
// CTA tile 128x128, BK=16, 256 threads = 8 warps, warp tile 64x32 (mma m16n8k8 tf32)
__global__ __launch_bounds__(256) void proj_kernel(
    const float* __restrict__ X, const float* __restrict__ W,
    const float* __restrict__ bias, int which)
{
    __shared__ __align__(16) float As[16][132];   // k-major: As[k][m]
    __shared__ __align__(16) float Bs[16][132];   // k-major: Bs[k][n]
    float* out = (which == 0) ? g_qh : (which == 1) ? g_kh : g_vh;

    const int t = threadIdx.x;
    const int lane = t & 31, w = t >> 5;
    const int g = lane >> 2, tg = lane & 3;
    const int m0 = blockIdx.x * 128;
    const int n0 = blockIdx.y * 128;
    const int wm = (w & 1) * 64;       // warp m offset within tile
    const int wn = (w >> 1) * 32;      // warp n offset within tile

    float acc[4][4][4];
#pragma unroll
    for (int mt = 0; mt < 4; mt++)
#pragma unroll
        for (int nt = 0; nt < 4; nt++)
#pragma unroll
            for (int r = 0; r < 4; r++) acc[mt][nt][r] = 0.0f;

    const int lr = t >> 2;          // 0..63
    const int lk = (t & 3) * 4;     // 0,4,8,12

    for (int k0 = 0; k0 < ND; k0 += 16) {
#pragma unroll
        for (int half = 0; half < 2; half++) {
            const int rw = lr + half * 64;
            float4 av = *(const float4*)(X + (size_t)(m0 + rw) * ND + k0 + lk);
            As[lk + 0][rw] = f2tff(av.x); As[lk + 1][rw] = f2tff(av.y);
            As[lk + 2][rw] = f2tff(av.z); As[lk + 3][rw] = f2tff(av.w);
            float4 bv = *(const float4*)(W + (size_t)(n0 + rw) * ND + k0 + lk);
            Bs[lk + 0][rw] = f2tff(bv.x); Bs[lk + 1][rw] = f2tff(bv.y);
            Bs[lk + 2][rw] = f2tff(bv.z); Bs[lk + 3][rw] = f2tff(bv.w);
        }
        __syncthreads();
#pragma unroll
        for (int kk = 0; kk < 16; kk += 8) {
            unsigned a[4][4], b[4][2];
#pragma unroll
            for (int mt = 0; mt < 4; mt++) {
                const int m = wm + mt * 16 + g;
                a[mt][0] = __float_as_uint(As[kk + tg][m]);
                a[mt][1] = __float_as_uint(As[kk + tg][m + 8]);
                a[mt][2] = __float_as_uint(As[kk + 4 + tg][m]);
                a[mt][3] = __float_as_uint(As[kk + 4 + tg][m + 8]);
            }
#pragma unroll
            for (int nt = 0; nt < 4; nt++) {
                const int n = wn + nt * 8 + g;
                b[nt][0] = __float_as_uint(Bs[kk + tg][n]);
                b[nt][1] = __float_as_uint(Bs[kk + 4 + tg][n]);
            }
#pragma unroll
            for (int mt = 0; mt < 4; mt++)
#pragma unroll
                for (int nt = 0; nt < 4; nt++)
                    mma_tf32(acc[mt][nt], a[mt], b[nt]);
        }
        __syncthreads();
    }

    // epilogue: scatter with bias to [b,h,s,d]
#pragma unroll
    for (int mt = 0; mt < 4; mt++) {
#pragma unroll
        for (int rr = 0; rr < 2; rr++) {
            const int row = m0 + wm + mt * 16 + g + rr * 8;   // b*S+s
            const int b_ = row / NS, s = row % NS;
#pragma unroll
            for (int nt = 0; nt < 4; nt++) {
                const int col = n0 + wn + nt * 8 + tg * 2;     // h*64+d
                const int h = col >> 6, d = col & 63;
                float2 val;
                val.x = acc[mt][nt][rr * 2 + 0] + bias[col];
                val.y = acc[mt][nt][rr * 2 + 1] + bias[col + 1];
                *(float2*)&out[(((size_t)b_ * NH + h) * NS + s) * HD + d] = val;
            }
        }
    }
}

// ---------------- attention: one block per (b, h, 16-query tile) -------------------
// smem: scores[16][2052] | buf[64][68] (K/V chunk) | part[8][16][68] (Qs, PV partials) | inv_s
__global__ __launch_bounds__(256) void attn_kernel(const int* __restrict__ mask,
                                                   float* __restrict__ attn_out)
{
    extern __shared__ __align__(16) float sm[];
    float* scores = sm;                       // 16*2052 = 32832
    float* buf    = sm + 16 * SROW;           // 64*68  = 4352
    float* part   = buf + 64 * 68;            // 8*1088 = 8704
    float* inv_s  = part + 8 * 1088;          // 16

    const int t   = threadIdx.x;
    const int lane = t & 31, w = t >> 5;
    const int g = lane >> 2, tg = lane & 3;
    const int bid = blockIdx.x;
    const int qt = bid & 127;
    const int h  = (bid >> 7) & 15;
    const int b  = bid >> 11;
    const int q0 = qt * 16;

    const size_t bh = (size_t)(b * NH + h);
    const float* qbase = g_qh + bh * NS * HD;
    const float* kbase = g_kh + bh * NS * HD;
    const float* vbase = g_vh + bh * NS * HD;

    // ---- stage Q (scaled, tf32) into part region as Qs[16][68] ----
    {
        const int row = t >> 4, kd = (t & 15) * 4;
        float4 qv = *(const float4*)(qbase + (size_t)(q0 + row) * HD + kd);
        float4 sv;
        sv.x = f2tff(qv.x * SCALE); sv.y = f2tff(qv.y * SCALE);
        sv.z = f2tff(qv.z * SCALE); sv.w = f2tff(qv.w * SCALE);
        *(float4*)(part + row * 68 + kd) = sv;
    }
    __syncthreads();

    // preload Q fragments for all 8 k-steps (reused for every key chunk)
    unsigned aq[8][4];
#pragma unroll
    for (int kk = 0; kk < 8; kk++) {
        aq[kk][0] = __float_as_uint(part[g * 68 + kk * 8 + tg]);
        aq[kk][1] = __float_as_uint(part[(g + 8) * 68 + kk * 8 + tg]);
        aq[kk][2] = __float_as_uint(part[g * 68 + kk * 8 + 4 + tg]);
        aq[kk][3] = __float_as_uint(part[(g + 8) * 68 + kk * 8 + 4 + tg]);
    }

    // ---- phase 1: scores = (q*scale) @ K^T via mma ----
    for (int jc = 0; jc < 32; jc++) {
        const int j0 = jc * 64;
#pragma unroll
        for (int r = 0; r < 4; r++) {
            const int idx = t + 256 * r;
            const int key = idx >> 4, kd = (idx & 15) * 4;
            float4 kv = *(const float4*)(kbase + (size_t)(j0 + key) * HD + kd);
            float4 s4;
            s4.x = f2tff(kv.x); s4.y = f2tff(kv.y);
            s4.z = f2tff(kv.z); s4.w = f2tff(kv.w);
            *(float4*)(buf + key * 68 + kd) = s4;
        }
        __syncthreads();
        float c[4] = {0.f, 0.f, 0.f, 0.f};
#pragma unroll
        for (int kk = 0; kk < 8; kk++) {
            unsigned bb[2];
            bb[0] = __float_as_uint(buf[(w * 8 + g) * 68 + kk * 8 + tg]);
            bb[1] = __float_as_uint(buf[(w * 8 + g) * 68 + kk * 8 + 4 + tg]);
            mma_tf32(c, aq[kk], bb);
        }
        const int col = j0 + w * 8 + tg * 2;
        *(float2*)&scores[g * SROW + col]       = make_float2(c[0], c[1]);
        *(float2*)&scores[(g + 8) * SROW + col] = make_float2(c[2], c[3]);
        __syncthreads();
    }

    // ---- phase 2: masks + softmax (warp w owns rows 2w, 2w+1) ----
    {
        for (int rr = 0; rr < 2; rr++) {
            const int i = w * 2 + rr;
            const int qrow = q0 + i;
            const int* mrow = mask + ((size_t)b * NS + qrow) * NS;
            float mx = -3.0e38f;
            for (int k = lane; k < NS; k += 32) {
                float sv = scores[i * SROW + k];
                sv += (1.0f - (float)mrow[k]) * NEGV;   // padding mask adder
                if (k > qrow) sv += NEGV;               // causal adder
                scores[i * SROW + k] = sv;
                mx = fmaxf(mx, sv);
            }
#pragma unroll
            for (int o = 16; o > 0; o >>= 1) mx = fmaxf(mx, __shfl_xor_sync(0xffffffffu, mx, o));
            float sum = 0.0f;
            for (int k = lane; k < NS; k += 32) {
                const float p = __expf(scores[i * SROW + k] - mx);
                scores[i * SROW + k] = p;
                sum += p;
            }
#pragma unroll
            for (int o = 16; o > 0; o >>= 1) sum += __shfl_xor_sync(0xffffffffu, sum, o);
            if (lane == 0) inv_s[i] = 1.0f / sum;
        }
        __syncthreads();
    }

    // ---- phase 3: write normalized attention probabilities ----
    if (attn_out) {
        for (int idx = t; idx < 16 * NS; idx += 256) {
            const int i = idx >> 11, j = idx & (NS - 1);
            attn_out[(bh * NS + q0 + i) * (size_t)NS + j] = scores[i * SROW + j] * inv_s[i];
        }
    }

    // ---- phase 4: out = P @ V via mma; warps split keys, smem partial reduce ----
    {
        float pc[8][4];
#pragma unroll
        for (int nt = 0; nt < 8; nt++)
#pragma unroll
            for (int r = 0; r < 4; r++) pc[nt][r] = 0.0f;

        for (int jc = 0; jc < 32; jc++) {
            const int j0 = jc * 64;
#pragma unroll
            for (int r = 0; r < 4; r++) {
                const int idx = t + 256 * r;
                const int key = idx >> 4, kd = (idx & 15) * 4;
                float4 vv = *(const float4*)(vbase + (size_t)(j0 + key) * HD + kd);
                float4 s4;
                s4.x = f2tff(vv.x); s4.y = f2tff(vv.y);
                s4.z = f2tff(vv.z); s4.w = f2tff(vv.w);
                *(float4*)(buf + key * 68 + kd) = s4;
            }
            __syncthreads();
            // warp w handles the 8 keys [j0 + 8w, j0 + 8w + 8) == one k-step
            unsigned a[4];
            const int krow = j0 + w * 8;
            a[0] = f2tf(scores[g * SROW + krow + tg]);
            a[1] = f2tf(scores[(g + 8) * SROW + krow + tg]);
            a[2] = f2tf(scores[g * SROW + krow + 4 + tg]);
            a[3] = f2tf(scores[(g + 8) * SROW + krow + 4 + tg]);
#pragma unroll
            for (int nt = 0; nt < 8; nt++) {
                unsigned bb[2];
                bb[0] = __float_as_uint(buf[(w * 8 + tg) * 68 + nt * 8 + g]);
                bb[1] = __float_as_uint(buf[(w * 8 + 4 + tg) * 68 + nt * 8 + g]);
                mma_tf32(pc[nt], a, bb);
            }
            __syncthreads();
        }

        // write per-warp partials (reuse part region; Qs no longer needed)
#pragma unroll
        for (int nt = 0; nt < 8; nt++) {
            const int col = nt * 8 + tg * 2;
            *(float2*)&part[w * 1088 + g * 68 + col]       = make_float2(pc[nt][0], pc[nt][1]);
            *(float2*)&part[w * 1088 + (g + 8) * 68 + col] = make_float2(pc[nt][2], pc[nt][3]);
        }
        __syncthreads();
        for (int idx = t; idx < 1024; idx += 256) {
            const int i = idx >> 6, dd = idx & 63;
            float s = 0.0f;
#pragma unroll
            for (int ww = 0; ww < 8; ww++) s += part[ww * 1088 + i * 68 + dd];
            g_ao[((size_t)b * NS + q0 + i) * ND + h * HD + dd] = s * inv_s[i];
        }
    }
}

// ---------------- residual + LayerNorm, one block per (b,s) row --------------------
__global__ __launch_bounds__(256) void ln_kernel(const float* __restrict__ resid,
                                                 const float* __restrict__ gam,
                                                 const float* __restrict__ bet,
                                                 float* __restrict__ out)
{
    __shared__ float xb[ND];
    __shared__ float red[8];
    const int r = blockIdx.x;
    const int t = threadIdx.x;
    const int lane = t & 31, w = t >> 5;
    const size_t base = (size_t)r * ND;

    float lsum = 0.0f;
    for (int j = t; j < ND; j += 256) {
        const float x = g_ao[base + j] + resid[base + j];
        xb[j] = x;
        lsum += x;
    }
#pragma unroll
    for (int o = 16; o > 0; o >>= 1) lsum += __shfl_xor_sync(0xffffffffu, lsum, o);
    if (lane == 0) red[w] = lsum;
    __syncthreads();
    float tot = 0.0f;
#pragma unroll
    for (int w2 = 0; w2 < 8; w2++) tot += red[w2];
    const float mu = tot * (1.0f / ND);
    __syncthreads();

    float lv = 0.0f;
    for (int j = t; j < ND; j += 256) {
        const float dd = xb[j] - mu;
        lv += dd * dd;
    }
#pragma unroll
    for (int o = 16; o > 0; o >>= 1) lv += __shfl_xor_sync(0xffffffffu, lv, o);
    if (lane == 0) red[w] = lv;
    __syncthreads();
    float vtot = 0.0f;
#pragma unroll
    for (int w2 = 0; w2 < 8; w2++) vtot += red[w2];
    const float rstd = rsqrtf(vtot * (1.0f / ND) + 1e-5f);

    for (int j = t; j < ND; j += 256)
        out[base + j] = (xb[j] - mu) * rstd * gam[j] + bet[j];
}

// ---------------- launch -----------------------------------------------------------
extern "C" void kernel_launch(void* const* d_in, const int* in_sizes, int n_in,
                              void* d_out, int out_size)
{
    const float* q    = (const float*)d_in[0];
    const float* k    = (const float*)d_in[1];
    const float* v    = (const float*)d_in[2];
    const int*   mask = (const int*)  d_in[3];
    const float* Wq   = (const float*)d_in[4];
    const float* bq   = (const float*)d_in[5];
    const float* Wk   = (const float*)d_in[6];
    const float* bk   = (const float*)d_in[7];
    const float* Wv   = (const float*)d_in[8];
    const float* bv   = (const float*)d_in[9];
    const float* ln_g = (const float*)d_in[10];
    const float* ln_b = (const float*)d_in[11];
    float* out = (float*)d_out;

    const int smem_bytes = (16 * SROW + 64 * 68 + 8 * 1088 + 16) * (int)sizeof(float); // 183,680 B
    cudaFuncSetAttribute(attn_kernel, cudaFuncAttributeMaxDynamicSharedMemorySize, smem_bytes);

    dim3 pg(64, 8);  // M=8192/128, N=1024/128
    proj_kernel<<<pg, 256>>>(q, Wq, bq, 0);
    proj_kernel<<<pg, 256>>>(k, Wk, bk, 1);
    proj_kernel<<<pg, 256>>>(v, Wv, bv, 2);

    float* attn = nullptr;
    const long long need = (long long)NB * NS * ND + (long long)NB * NH * NS * NS;
    if ((long long)out_size >= need) attn = out + (size_t)NB * NS * ND;

    attn_kernel<<<NB * NH * (NS / 16), 256, smem_bytes>>>(mask, attn);
    ln_kernel<<<NB * NS, 256>>>(q, ln_g, ln_b, out);
}

// round 8
// speedup vs baseline: 2.1364x; 1.4496x over previous
#include <cuda_runtime.h>

#define NB 4
#define NS 2048
#define ND 1024
#define NH 16
#define HD 64
#define NEGV (-10000.0f)
#define SCALE 0.125f
#define SROW 2052   // padded score row stride; %32==4 (conflict-free), %4==0 (float4)

// ---------------- scratch (static device arrays; no runtime allocation) ------------
__device__ float g_qh[NB * NH * NS * HD];
__device__ float g_kh[NB * NH * NS * HD];
__device__ float g_vh[NB * NH * NS * HD];
__device__ float g_ao[NB * NS * ND];

// ---------------- tf32 helpers -----------------------------------------------------
__device__ __forceinline__ unsigned f2tf(float x) {
    unsigned u; asm("cvt.rna.tf32.f32 %0, %1;" : "=r"(u) : "f"(x)); return u;
}
__device__ __forceinline__ float f2tff(float x) { return __uint_as_float(f2tf(x)); }

__device__ __forceinline__ void mma_tf32(float c[4], const unsigned a[4], const unsigned b[2]) {
    asm volatile(
        "mma.sync.aligned.m16n8k8.row.col.f32.tf32.tf32.f32 "
        "{%0,%1,%2,%3}, {%4,%5,%6,%7}, {%8,%9}, {%0,%1,%2,%3};"
        : "+f"(c[0]), "+f"(c[1]), "+f"(c[2]), "+f"(c[3])
        : "r"(a[0]), "r"(a[1]), "r"(a[2]), "r"(a[3]), "r"(b[0]), "r"(b[1]));
}

// ---------------- QKV projection: Y = X @ W^T + b, scattered to [b,h,s,d] ----------
// CTA 128x128, BK=16, 256 thr = 8 warps, warp tile 64x32; double-buffered smem.
__global__ __launch_bounds__(256) void proj_kernel(
    const float* __restrict__ X, const float* __restrict__ W,
    const float* __restrict__ bias, int which)
{
    __shared__ __align__(16) float As[2][16][132];
    __shared__ __align__(16) float Bs[2][16][132];
    float* out = (which == 0) ? g_qh : (which == 1) ? g_kh : g_vh;

    const int t = threadIdx.x;
    const int lane = t & 31, w = t >> 5;
    const int g = lane >> 2, tg = lane & 3;
    const int m0 = blockIdx.x * 128;
    const int n0 = blockIdx.y * 128;
    const int wm = (w & 1) * 64;
    const int wn = (w >> 1) * 32;

    float acc[4][4][4];
#pragma unroll
    for (int mt = 0; mt < 4; mt++)
#pragma unroll
        for (int nt = 0; nt < 4; nt++)
#pragma unroll
            for (int r = 0; r < 4; r++) acc[mt][nt][r] = 0.0f;

    const int lr = t >> 2;
    const int lk = (t & 3) * 4;

    int stage = 0;
    for (int k0 = 0; k0 < ND; k0 += 16, stage ^= 1) {
#pragma unroll
        for (int half = 0; half < 2; half++) {
            const int rw = lr + half * 64;
            float4 av = *(const float4*)(X + (size_t)(m0 + rw) * ND + k0 + lk);
            As[stage][lk + 0][rw] = f2tff(av.x); As[stage][lk + 1][rw] = f2tff(av.y);
            As[stage][lk + 2][rw] = f2tff(av.z); As[stage][lk + 3][rw] = f2tff(av.w);
            float4 bv = *(const float4*)(W + (size_t)(n0 + rw) * ND + k0 + lk);
            Bs[stage][lk + 0][rw] = f2tff(bv.x); Bs[stage][lk + 1][rw] = f2tff(bv.y);
            Bs[stage][lk + 2][rw] = f2tff(bv.z); Bs[stage][lk + 3][rw] = f2tff(bv.w);
        }
        __syncthreads();   // single barrier/iter; overwrite at k0+2 fenced by barrier at k0+1
#pragma unroll
        for (int kk = 0; kk < 16; kk += 8) {
            unsigned a[4][4], b[4][2];
#pragma unroll
            for (int mt = 0; mt < 4; mt++) {
                const int m = wm + mt * 16 + g;
                a[mt][0] = __float_as_uint(As[stage][kk + tg][m]);
                a[mt][1] = __float_as_uint(As[stage][kk + tg][m + 8]);
                a[mt][2] = __float_as_uint(As[stage][kk + 4 + tg][m]);
                a[mt][3] = __float_as_uint(As[stage][kk + 4 + tg][m + 8]);
            }
#pragma unroll
            for (int nt = 0; nt < 4; nt++) {
                const int n = wn + nt * 8 + g;
                b[nt][0] = __float_as_uint(Bs[stage][kk + tg][n]);
                b[nt][1] = __float_as_uint(Bs[stage][kk + 4 + tg][n]);
            }
#pragma unroll
            for (int mt = 0; mt < 4; mt++)
#pragma unroll
                for (int nt = 0; nt < 4; nt++)
                    mma_tf32(acc[mt][nt], a[mt], b[nt]);
        }
    }

#pragma unroll
    for (int mt = 0; mt < 4; mt++) {
#pragma unroll
        for (int rr = 0; rr < 2; rr++) {
            const int row = m0 + wm + mt * 16 + g + rr * 8;
            const int b_ = row / NS, s = row % NS;
#pragma unroll
            for (int nt = 0; nt < 4; nt++) {
                const int col = n0 + wn + nt * 8 + tg * 2;
                const int h = col >> 6, d = col & 63;
                float2 val;
                val.x = acc[mt][nt][rr * 2 + 0] + bias[col];
                val.y = acc[mt][nt][rr * 2 + 1] + bias[col + 1];
                *(float2*)&out[(((size_t)b_ * NH + h) * NS + s) * HD + d] = val;
            }
        }
    }
}

// ---------------- attention: one block (512 thr, 16 warps) per (b,h,16-query tile) --
// smem: scores[16][2052] | buf0[128][68] | buf1[128][68] | inv_s[16]
// part[8][16][68] aliases buf0 (used only after post-loop barrier in phase 4)
__global__ __launch_bounds__(512) void attn_kernel(const int* __restrict__ mask,
                                                   float* __restrict__ attn_out)
{
    extern __shared__ __align__(16) float sm[];
    float* scores = sm;                        // 16*2052 = 32832
    float* buf0   = sm + 16 * SROW;            // 128*68  = 8704
    float* buf1   = buf0 + 128 * 68;           // 128*68  = 8704
    float* inv_s  = buf1 + 128 * 68;           // 16
    float* part   = buf0;                      // alias (phase-4 partials)

    const int t    = threadIdx.x;
    const int lane = t & 31, w = t >> 5;       // w: 0..15
    const int g = lane >> 2, tg = lane & 3;
    const int bid = blockIdx.x;
    const int qt = bid & 127;
    const int h  = (bid >> 7) & 15;
    const int b  = bid >> 11;
    const int q0 = qt * 16;

    const size_t bh = (size_t)(b * NH + h);
    const float* qbase = g_qh + bh * NS * HD;
    const float* kbase = g_kh + bh * NS * HD;
    const float* vbase = g_vh + bh * NS * HD;

    // ---- stage Q (scaled, tf32) into buf0 as Qs[16][68], preload fragments ----
    if (t < 256) {
        const int row = t >> 4, kd = (t & 15) * 4;
        float4 qv = *(const float4*)(qbase + (size_t)(q0 + row) * HD + kd);
        float4 sv;
        sv.x = f2tff(qv.x * SCALE); sv.y = f2tff(qv.y * SCALE);
        sv.z = f2tff(qv.z * SCALE); sv.w = f2tff(qv.w * SCALE);
        *(float4*)(buf0 + row * 68 + kd) = sv;
    }
    __syncthreads();
    unsigned aq[8][4];
#pragma unroll
    for (int kk = 0; kk < 8; kk++) {
        aq[kk][0] = __float_as_uint(buf0[g * 68 + kk * 8 + tg]);
        aq[kk][1] = __float_as_uint(buf0[(g + 8) * 68 + kk * 8 + tg]);
        aq[kk][2] = __float_as_uint(buf0[g * 68 + kk * 8 + 4 + tg]);
        aq[kk][3] = __float_as_uint(buf0[(g + 8) * 68 + kk * 8 + 4 + tg]);
    }
    __syncthreads();

    // ---- phase 1: scores = (q*scale) @ K^T, 128-key chunks, double-buffered ----
    for (int jc = 0; jc < 16; jc++) {
        const int j0 = jc * 128;
        float* bufc = (jc & 1) ? buf1 : buf0;
#pragma unroll
        for (int r = 0; r < 4; r++) {
            const int idx = t + 512 * r;
            const int key = idx >> 4, kd = (idx & 15) * 4;
            float4 kv = *(const float4*)(kbase + (size_t)(j0 + key) * HD + kd);
            float4 s4;
            s4.x = f2tff(kv.x); s4.y = f2tff(kv.y);
            s4.z = f2tff(kv.z); s4.w = f2tff(kv.w);
            *(float4*)(bufc + key * 68 + kd) = s4;
        }
        __syncthreads();
        float c0[4] = {0.f, 0.f, 0.f, 0.f}, c1[4] = {0.f, 0.f, 0.f, 0.f};
#pragma unroll
        for (int kp = 0; kp < 4; kp++) {
            unsigned b0[2], b1[2];
            b0[0] = __float_as_uint(bufc[(w * 8 + g) * 68 + (2 * kp) * 8 + tg]);
            b0[1] = __float_as_uint(bufc[(w * 8 + g) * 68 + (2 * kp) * 8 + 4 + tg]);
            b1[0] = __float_as_uint(bufc[(w * 8 + g) * 68 + (2 * kp + 1) * 8 + tg]);
            b1[1] = __float_as_uint(bufc[(w * 8 + g) * 68 + (2 * kp + 1) * 8 + 4 + tg]);
            mma_tf32(c0, aq[2 * kp], b0);
            mma_tf32(c1, aq[2 * kp + 1], b1);
        }
        const int col = j0 + w * 8 + tg * 2;
        *(float2*)&scores[g * SROW + col]       = make_float2(c0[0] + c1[0], c0[1] + c1[1]);
        *(float2*)&scores[(g + 8) * SROW + col] = make_float2(c0[2] + c1[2], c0[3] + c1[3]);
    }
    __syncthreads();

    // ---- phase 2: masks + softmax; warp w owns row w; vectorized ----
    {
        const int i = w;
        const int qrow = q0 + i;
        const int* mrow = mask + ((size_t)b * NS + qrow) * NS;
        float mx = -3.0e38f;
        for (int k4 = lane * 4; k4 < NS; k4 += 128) {
            int4 m4 = *(const int4*)(mrow + k4);
            float4 s4 = *(float4*)(scores + i * SROW + k4);
            s4.x += (1.0f - (float)m4.x) * NEGV + ((k4 + 0 > qrow) ? NEGV : 0.0f);
            s4.y += (1.0f - (float)m4.y) * NEGV + ((k4 + 1 > qrow) ? NEGV : 0.0f);
            s4.z += (1.0f - (float)m4.z) * NEGV + ((k4 + 2 > qrow) ? NEGV : 0.0f);
            s4.w += (1.0f - (float)m4.w) * NEGV + ((k4 + 3 > qrow) ? NEGV : 0.0f);
            *(float4*)(scores + i * SROW + k4) = s4;
            mx = fmaxf(mx, fmaxf(fmaxf(s4.x, s4.y), fmaxf(s4.z, s4.w)));
        }
#pragma unroll
        for (int o = 16; o > 0; o >>= 1) mx = fmaxf(mx, __shfl_xor_sync(0xffffffffu, mx, o));
        float sum = 0.0f;
        for (int k4 = lane * 4; k4 < NS; k4 += 128) {
            float4 s4 = *(float4*)(scores + i * SROW + k4);
            s4.x = __expf(s4.x - mx); s4.y = __expf(s4.y - mx);
            s4.z = __expf(s4.z - mx); s4.w = __expf(s4.w - mx);
            *(float4*)(scores + i * SROW + k4) = s4;
            sum += (s4.x + s4.y) + (s4.z + s4.w);
        }
#pragma unroll
        for (int o = 16; o > 0; o >>= 1) sum += __shfl_xor_sync(0xffffffffu, sum, o);
        if (lane == 0) inv_s[i] = 1.0f / sum;
    }
    __syncthreads();

    // ---- phase 3: write normalized attention probabilities (float4) ----
    if (attn_out) {
        for (int idx = t; idx < 16 * 512; idx += 512) {
            const int i = idx >> 9, j = (idx & 511) * 4;
            float4 p = *(float4*)(scores + i * SROW + j);
            const float iv = inv_s[i];
            p.x *= iv; p.y *= iv; p.z *= iv; p.w *= iv;
            *(float4*)&attn_out[(bh * NS + q0 + i) * (size_t)NS + j] = p;
        }
    }

    // ---- phase 4: out = P @ V; warp w -> key-group (w>>1), d-half (w&1)*32 ----
    {
        const int kg = w >> 1, dh = (w & 1) * 32;
        float pc[4][4];
#pragma unroll
        for (int nt = 0; nt < 4; nt++)
#pragma unroll
            for (int r = 0; r < 4; r++) pc[nt][r] = 0.0f;

        for (int jc = 0; jc < 16; jc++) {
            const int j0 = jc * 128;
            float* bufc = (jc & 1) ? buf1 : buf0;
#pragma unroll
            for (int r = 0; r < 4; r++) {
                const int idx = t + 512 * r;
                const int key = idx >> 4, kd = (idx & 15) * 4;
                float4 vv = *(const float4*)(vbase + (size_t)(j0 + key) * HD + kd);
                float4 s4;
                s4.x = f2tff(vv.x); s4.y = f2tff(vv.y);
                s4.z = f2tff(vv.z); s4.w = f2tff(vv.w);
                *(float4*)(bufc + key * 68 + kd) = s4;
            }
            __syncthreads();
#pragma unroll
            for (int s = 0; s < 2; s++) {
                const int kr = j0 + kg * 16 + s * 8;      // global key base
                const int lk = kg * 16 + s * 8;           // local in bufc
                unsigned a[4];
                a[0] = f2tf(scores[g * SROW + kr + tg]);
                a[1] = f2tf(scores[(g + 8) * SROW + kr + tg]);
                a[2] = f2tf(scores[g * SROW + kr + 4 + tg]);
                a[3] = f2tf(scores[(g + 8) * SROW + kr + 4 + tg]);
#pragma unroll
                for (int nt = 0; nt < 4; nt++) {
                    unsigned bb[2];
                    bb[0] = __float_as_uint(bufc[(lk + tg) * 68 + dh + nt * 8 + g]);
                    bb[1] = __float_as_uint(bufc[(lk + 4 + tg) * 68 + dh + nt * 8 + g]);
                    mma_tf32(pc[nt], a, bb);
                }
            }
        }
        __syncthreads();   // all MMA reads of buf0/buf1 done before partials alias buf0

#pragma unroll
        for (int nt = 0; nt < 4; nt++) {
            const int col = dh + nt * 8 + tg * 2;
            *(float2*)&part[kg * 1088 + g * 68 + col]       = make_float2(pc[nt][0], pc[nt][1]);
            *(float2*)&part[kg * 1088 + (g + 8) * 68 + col] = make_float2(pc[nt][2], pc[nt][3]);
        }
        __syncthreads();
        for (int idx = t; idx < 1024; idx += 512) {
            const int i = idx >> 6, dd = idx & 63;
            float s = 0.0f;
#pragma unroll
            for (int ww = 0; ww < 8; ww++) s += part[ww * 1088 + i * 68 + dd];
            g_ao[((size_t)b * NS + q0 + i) * ND + h * HD + dd] = s * inv_s[i];
        }
    }
}

// ---------------- residual + LayerNorm, one block per (b,s) row --------------------
__global__ __launch_bounds__(256) void ln_kernel(const float* __restrict__ resid,
                                                 const float* __restrict__ gam,
                                                 const float* __restrict__ bet,
                                                 float* __restrict__ out)
{
    __shared__ float xb[ND];
    __shared__ float red[8];
    const int r = blockIdx.x;
    const int t = threadIdx.x;
    const int lane = t & 31, w = t >> 5;
    const size_t base = (size_t)r * ND;

    float lsum = 0.0f;
    for (int j = t; j < ND; j += 256) {
        const float x = g_ao[base + j] + resid[base + j];
        xb[j] = x;
        lsum += x;
    }
#pragma unroll
    for (int o = 16; o > 0; o >>= 1) lsum += __shfl_xor_sync(0xffffffffu, lsum, o);
    if (lane == 0) red[w] = lsum;
    __syncthreads();
    float tot = 0.0f;
#pragma unroll
    for (int w2 = 0; w2 < 8; w2++) tot += red[w2];
    const float mu = tot * (1.0f / ND);
    __syncthreads();

    float lv = 0.0f;
    for (int j = t; j < ND; j += 256) {
        const float dd = xb[j] - mu;
        lv += dd * dd;
    }
#pragma unroll
    for (int o = 16; o > 0; o >>= 1) lv += __shfl_xor_sync(0xffffffffu, lv, o);
    if (lane == 0) red[w] = lv;
    __syncthreads();
    float vtot = 0.0f;
#pragma unroll
    for (int w2 = 0; w2 < 8; w2++) vtot += red[w2];
    const float rstd = rsqrtf(vtot * (1.0f / ND) + 1e-5f);

    for (int j = t; j < ND; j += 256)
        out[base + j] = (xb[j] - mu) * rstd * gam[j] + bet[j];
}

// ---------------- launch -----------------------------------------------------------
extern "C" void kernel_launch(void* const* d_in, const int* in_sizes, int n_in,
                              void* d_out, int out_size)
{
    const float* q    = (const float*)d_in[0];
    const float* k    = (const float*)d_in[1];
    const float* v    = (const float*)d_in[2];
    const int*   mask = (const int*)  d_in[3];
    const float* Wq   = (const float*)d_in[4];
    const float* bq   = (const float*)d_in[5];
    const float* Wk   = (const float*)d_in[6];
    const float* bk   = (const float*)d_in[7];
    const float* Wv   = (const float*)d_in[8];
    const float* bv   = (const float*)d_in[9];
    const float* ln_g = (const float*)d_in[10];
    const float* ln_b = (const float*)d_in[11];
    float* out = (float*)d_out;

    const int smem_bytes = (16 * SROW + 2 * 128 * 68 + 16) * (int)sizeof(float); // 201,024 B
    cudaFuncSetAttribute(attn_kernel, cudaFuncAttributeMaxDynamicSharedMemorySize, smem_bytes);

    dim3 pg(64, 8);
    proj_kernel<<<pg, 256>>>(q, Wq, bq, 0);
    proj_kernel<<<pg, 256>>>(k, Wk, bk, 1);
    proj_kernel<<<pg, 256>>>(v, Wv, bv, 2);

    float* attn = nullptr;
    const long long need = (long long)NB * NS * ND + (long long)NB * NH * NS * NS;
    if ((long long)out_size >= need) attn = out + (size_t)NB * NS * ND;

    attn_kernel<<<NB * NH * (NS / 16), 512, smem_bytes>>>(mask, attn);
    ln_kernel<<<NB * NS, 256>>>(q, ln_g, ln_b, out);
}